// round 3
// baseline (speedup 1.0000x reference)
#include <cuda_runtime.h>
#include <math.h>

#define N 512
#define D 256
#define BT 32
#define NTILES 16            // N / BT
#define NBLK 136             // NTILES*(NTILES+1)/2
#define MAXP 64              // max positives per anchor (actual ~8-20)
#define FULL 0xFFFFFFFFu

// __device__ scratch (allocation-free rule)
__device__ float g_alist[N * MAXP];     // a_p = d_ip + margin, per anchor
__device__ int   g_npos[N];
__device__ float g_pS[NTILES * N];      // per-(tile, anchor) partial sums
__device__ float g_pC[NTILES * N];      // per-(tile, anchor) partial counts
__device__ int   g_bar1;                // phase-0 publish barrier
__device__ int   g_bar2;                // completion counter

__global__ void __launch_bounds__(256, 1)
fused_kernel(const float* __restrict__ x, const int* __restrict__ labels,
             float* __restrict__ out) {
    __shared__ int   lab[N];
    __shared__ float As[BT][BT + 1];
    __shared__ float Bs[BT][BT + 1];
    __shared__ float s_d[BT][BT + 1];
    __shared__ float sqi[BT];
    __shared__ float sqj[BT];
    __shared__ float fsred[8];
    __shared__ float fcred[8];
    __shared__ int   s_last;

    const int t = threadIdx.x;      // 0..255
    const int lane = t & 31;
    const int w = t >> 5;           // 0..7

    // triangle decode (bi >= bj)
    int b = blockIdx.x;
    int bi = (int)((sqrtf(8.f * (float)b + 1.f) - 1.f) * 0.5f);
    while ((bi + 1) * (bi + 2) / 2 <= b) bi++;
    while (bi * (bi + 1) / 2 > b) bi--;
    const int bj = b - bi * (bi + 1) / 2;
    const int i0 = bi * BT;
    const int j0 = bj * BT;

    // labels -> smem
    reinterpret_cast<int2*>(lab)[t] = reinterpret_cast<const int2*>(labels)[t];
    __syncthreads();

    // ---------------- Phase 0 (split warps) ----------------
    if (w < 4) {
        // warps 0-3: positive lists for anchors a = blockIdx*4 + w
        int a = blockIdx.x * 4 + w;
        if (a < N) {
            const int li = lab[a];
            float xa[8];
            float sqa = 0.f;
#pragma unroll
            for (int c = 0; c < 8; c++) {
                xa[c] = x[a * D + lane + 32 * c];
                sqa += xa[c] * xa[c];
            }
#pragma unroll
            for (int o = 16; o > 0; o >>= 1) sqa += __shfl_xor_sync(FULL, sqa, o);

            int np = 0;
            for (int cb = 0; cb < 16; cb++) {
                int j = cb * 32 + lane;
                unsigned m = __ballot_sync(FULL, (lab[j] == li) && (j != a));
                while (m) {
                    int bit = __ffs(m) - 1;
                    m &= m - 1;
                    const float* xj = x + (cb * 32 + bit) * D;
                    float dot = 0.f, sqp = 0.f;
#pragma unroll
                    for (int c = 0; c < 8; c++) {
                        float v = xj[lane + 32 * c];
                        dot += xa[c] * v;
                        sqp += v * v;
                    }
#pragma unroll
                    for (int o = 16; o > 0; o >>= 1) {
                        dot += __shfl_down_sync(FULL, dot, o);
                        sqp += __shfl_down_sync(FULL, sqp, o);
                    }
                    if (lane == 0 && np < MAXP)
                        g_alist[a * MAXP + np] =
                            sqrtf(fmaxf(sqa + sqp - 2.f * dot, 1e-16f)) + 1.0f;
                    np++;
                }
            }
            if (lane == 0) g_npos[a] = (np > MAXP) ? MAXP : np;
        }
    } else {
        // warps 4-7: sq norms for the 64 tile rows
        int wr = w - 4;
#pragma unroll
        for (int rr = 0; rr < 16; rr++) {
            int r = wr * 16 + rr;                         // 0..63
            int gr = (r < 32) ? (i0 + r) : (j0 + r - 32);
            const float* row = x + gr * D;
            float s = 0.f;
#pragma unroll
            for (int c = 0; c < 8; c++) { float v = row[lane + 32 * c]; s += v * v; }
#pragma unroll
            for (int o = 16; o > 0; o >>= 1) s += __shfl_down_sync(FULL, s, o);
            if (lane == 0) { if (r < 32) sqi[r] = s; else sqj[r - 32] = s; }
        }
    }
    __syncthreads();
    if (t == 0) {                       // publish g_alist/g_npos (release)
        __threadfence();
        atomicAdd(&g_bar1, 1);
    }

    // ---------------- GEMM phase (overlaps other blocks' phase 0) ----------
    const int tx = t & 15;
    const int ty = t >> 4;
    const int lr = t >> 3;              // loader row 0..31
    const int lc = (t & 7) * 4;         // loader col 0,4,..,28

    float acc00 = 0.f, acc01 = 0.f, acc10 = 0.f, acc11 = 0.f;
    for (int kk = 0; kk < D; kk += BT) {
        float4 av = *reinterpret_cast<const float4*>(x + (i0 + lr) * D + kk + lc);
        float4 bv = *reinterpret_cast<const float4*>(x + (j0 + lr) * D + kk + lc);
        As[lr][lc + 0] = av.x; As[lr][lc + 1] = av.y;
        As[lr][lc + 2] = av.z; As[lr][lc + 3] = av.w;
        Bs[lr][lc + 0] = bv.x; Bs[lr][lc + 1] = bv.y;
        Bs[lr][lc + 2] = bv.z; Bs[lr][lc + 3] = bv.w;
        __syncthreads();
#pragma unroll
        for (int k = 0; k < BT; k++) {
            float a0 = As[2 * ty + 0][k];
            float a1 = As[2 * ty + 1][k];
            float b0 = Bs[2 * tx + 0][k];
            float b1 = Bs[2 * tx + 1][k];
            acc00 += a0 * b0; acc01 += a0 * b1;
            acc10 += a1 * b0; acc11 += a1 * b1;
        }
        __syncthreads();
    }

    {   // epilogue: d tile -> smem
        float si0 = sqi[2 * ty], si1 = sqi[2 * ty + 1];
        float sj0 = sqj[2 * tx], sj1 = sqj[2 * tx + 1];
        s_d[2 * ty + 0][2 * tx + 0] = sqrtf(fmaxf(si0 + sj0 - 2.f * acc00, 1e-16f));
        s_d[2 * ty + 0][2 * tx + 1] = sqrtf(fmaxf(si0 + sj1 - 2.f * acc01, 1e-16f));
        s_d[2 * ty + 1][2 * tx + 0] = sqrtf(fmaxf(si1 + sj0 - 2.f * acc10, 1e-16f));
        s_d[2 * ty + 1][2 * tx + 1] = sqrtf(fmaxf(si1 + sj1 - 2.f * acc11, 1e-16f));
    }

    // ---------------- grid barrier wait (should already be passed) --------
    if (t == 0) {
        volatile int* p = &g_bar1;
        while (*p < NBLK) { }
    }
    __syncthreads();
    __threadfence();                    // acquire

    // ---------------- hinge phase ----------------
    // row pass: warp w owns row-anchors r = 4w..4w+3, negatives = tile cols
#pragma unroll
    for (int rr = 0; rr < 4; rr++) {
        int r = w * 4 + rr;
        int A = i0 + r;
        bool neg = (lab[j0 + lane] != lab[A]);
        float dv = s_d[r][lane];
        int np = g_npos[A];
        float sum = 0.f; int cnt = 0;
        for (int p = 0; p < np; p++) {
            float aa = g_alist[A * MAXP + p];
            if (neg) {
                float v = aa - dv;
                if (v > 0.f) sum += v;
                if (v > 1e-16f) cnt++;
            }
        }
#pragma unroll
        for (int o = 16; o > 0; o >>= 1) {
            sum += __shfl_down_sync(FULL, sum, o);
            cnt += __shfl_down_sync(FULL, cnt, o);
        }
        if (lane == 0) {
            g_pS[bj * N + A] = sum;
            g_pC[bj * N + A] = (float)cnt;
        }
    }
    // col pass (mirror): skip on diagonal tiles (row pass already covers all)
    if (bi != bj) {
#pragma unroll
        for (int rr = 0; rr < 4; rr++) {
            int c = w * 4 + rr;
            int A = j0 + c;
            bool neg = (lab[i0 + lane] != lab[A]);
            float dv = s_d[lane][c];
            int np = g_npos[A];
            float sum = 0.f; int cnt = 0;
            for (int p = 0; p < np; p++) {
                float aa = g_alist[A * MAXP + p];
                if (neg) {
                    float v = aa - dv;
                    if (v > 0.f) sum += v;
                    if (v > 1e-16f) cnt++;
                }
            }
#pragma unroll
            for (int o = 16; o > 0; o >>= 1) {
                sum += __shfl_down_sync(FULL, sum, o);
                cnt += __shfl_down_sync(FULL, cnt, o);
            }
            if (lane == 0) {
                g_pS[bi * N + A] = sum;
                g_pC[bi * N + A] = (float)cnt;
            }
        }
    }

    // ---------------- completion + last-block final reduction -------------
    __syncthreads();
    if (t == 0) {
        __threadfence();
        int old = atomicAdd(&g_bar2, 1);
        s_last = (old == NBLK - 1) ? 1 : 0;
    }
    __syncthreads();

    if (s_last) {
        __threadfence();
        float s = 0.f, c = 0.f;
#pragma unroll
        for (int sl = 0; sl < NTILES; sl++) {
            s += g_pS[sl * N + t] + g_pS[sl * N + t + 256];
            c += g_pC[sl * N + t] + g_pC[sl * N + t + 256];
        }
#pragma unroll
        for (int o = 16; o > 0; o >>= 1) {
            s += __shfl_down_sync(FULL, s, o);
            c += __shfl_down_sync(FULL, c, o);
        }
        if (lane == 0) { fsred[w] = s; fcred[w] = c; }
        __syncthreads();
        if (t == 0) {
            float S = 0.f, C = 0.f;
#pragma unroll
            for (int k = 0; k < 8; k++) { S += fsred[k]; C += fcred[k]; }
            out[0] = S / (C + 1e-16f);
            g_bar1 = 0;                 // reset for next graph replay
            g_bar2 = 0;
        }
    }
}

extern "C" void kernel_launch(void* const* d_in, const int* in_sizes, int n_in,
                              void* d_out, int out_size) {
    const float* x      = (const float*)d_in[0];   // (512, 256) float32
    const int*   labels = (const int*)d_in[1];     // (512,) int32
    float* out = (float*)d_out;

    fused_kernel<<<NBLK, 256>>>(x, labels, out);
}

// round 4
// speedup vs baseline: 1.3582x; 1.3582x over previous
#include <cuda_runtime.h>
#include <math.h>

#define N 512
#define D 256
#define BT 32
#define NBLK_D 136            // 16*17/2 triangle of 32x32 tiles
#define NBLK_T 128            // triplet blocks, 4 anchors each
#define FULL 0xFFFFFFFFu

// __device__ scratch (allocation-free rule)
__device__ float g_dist[N * N];
__device__ float g_psum[NBLK_T];
__device__ float g_pcnt[NBLK_T];
__device__ int   g_done = 0;

// ---------------------------------------------------------------------------
// Kernel 1: fused sq-norms + symmetric distances.
// 136 triangle blocks, 128 threads, 32x32 tile, 4x2 register tile/thread.
// As[m][36] natural (STS.128), Bs[k][33] transposed (conflict-free).
// ---------------------------------------------------------------------------
__global__ void dist_kernel(const float* __restrict__ x) {
    __shared__ float As[BT][36];      // [m][k] pad 36 (rows 144B -> 16B aligned)
    __shared__ float Bs[BT][33];      // [k][n] pad 33
    __shared__ float sqi[BT];
    __shared__ float sqj[BT];

    const int t = threadIdx.x;        // 0..127
    const int lane = t & 31;
    const int w = t >> 5;             // 0..3

    // triangle decode (bi >= bj)
    int b = blockIdx.x;
    int bi = (int)((sqrtf(8.f * (float)b + 1.f) - 1.f) * 0.5f);
    while ((bi + 1) * (bi + 2) / 2 <= b) bi++;
    while (bi * (bi + 1) / 2 > b) bi--;
    const int bj = b - bi * (bi + 1) / 2;
    const int i0 = bi * BT;
    const int j0 = bj * BT;

    // --- sq norms: warp w handles 16 of the 64 rows ---
#pragma unroll
    for (int rr = 0; rr < 16; rr++) {
        int r = w * 16 + rr;                         // 0..63
        int gr = (r < 32) ? (i0 + r) : (j0 + r - 32);
        const float* row = x + gr * D;
        float s = 0.f;
#pragma unroll
        for (int c = 0; c < 8; c++) { float v = row[lane + 32 * c]; s += v * v; }
#pragma unroll
        for (int o = 16; o > 0; o >>= 1) s += __shfl_down_sync(FULL, s, o);
        if (lane == 0) { if (r < 32) sqi[r] = s; else sqj[r - 32] = s; }
    }

    // --- GEMM: compute threads tx=t&15 (j pair), ty=t>>4 (i quad) ---
    const int tx = t & 15;
    const int ty = t >> 4;
    const int lr = t >> 2;            // loader row 0..31
    const int lk = (t & 3) * 8;       // loader k offset 0,8,16,24

    float acc[4][2];
#pragma unroll
    for (int r = 0; r < 4; r++) { acc[r][0] = 0.f; acc[r][1] = 0.f; }

    const float* pa = x + (i0 + lr) * D + lk;
    const float* pb = x + (j0 + lr) * D + lk;

    // prefetch chunk 0
    float4 va0 = *reinterpret_cast<const float4*>(pa);
    float4 va1 = *reinterpret_cast<const float4*>(pa + 4);
    float4 vb0 = *reinterpret_cast<const float4*>(pb);
    float4 vb1 = *reinterpret_cast<const float4*>(pb + 4);

#pragma unroll
    for (int ch = 0; ch < D / BT; ch++) {
        __syncthreads();
        // A natural [m][k]: two STS.128
        *reinterpret_cast<float4*>(&As[lr][lk])     = va0;
        *reinterpret_cast<float4*>(&As[lr][lk + 4]) = va1;
        // B transposed [k][n]: 8 STS.32 (banks lk+c+lr cover all 32)
        Bs[lk + 0][lr] = vb0.x; Bs[lk + 1][lr] = vb0.y;
        Bs[lk + 2][lr] = vb0.z; Bs[lk + 3][lr] = vb0.w;
        Bs[lk + 4][lr] = vb1.x; Bs[lk + 5][lr] = vb1.y;
        Bs[lk + 6][lr] = vb1.z; Bs[lk + 7][lr] = vb1.w;
        __syncthreads();

        if (ch < D / BT - 1) {        // prefetch next chunk
            const float* na = pa + (ch + 1) * BT;
            const float* nb = pb + (ch + 1) * BT;
            va0 = *reinterpret_cast<const float4*>(na);
            va1 = *reinterpret_cast<const float4*>(na + 4);
            vb0 = *reinterpret_cast<const float4*>(nb);
            vb1 = *reinterpret_cast<const float4*>(nb + 4);
        }

#pragma unroll
        for (int k = 0; k < BT; k++) {
            float b0 = Bs[k][2 * tx + 0];
            float b1 = Bs[k][2 * tx + 1];
            float a0 = As[4 * ty + 0][k];
            float a1 = As[4 * ty + 1][k];
            float a2 = As[4 * ty + 2][k];
            float a3 = As[4 * ty + 3][k];
            acc[0][0] += a0 * b0; acc[0][1] += a0 * b1;
            acc[1][0] += a1 * b0; acc[1][1] += a1 * b1;
            acc[2][0] += a2 * b0; acc[2][1] += a2 * b1;
            acc[3][0] += a3 * b0; acc[3][1] += a3 * b1;
        }
    }

    // epilogue: dist + mirror
    const int jg = j0 + 2 * tx;
    float sj0 = sqj[2 * tx], sj1 = sqj[2 * tx + 1];
#pragma unroll
    for (int r = 0; r < 4; r++) {
        int ig = i0 + 4 * ty + r;
        float si = sqi[4 * ty + r];
        float d0 = sqrtf(fmaxf(si + sj0 - 2.f * acc[r][0], 1e-16f));
        float d1 = sqrtf(fmaxf(si + sj1 - 2.f * acc[r][1], 1e-16f));
        *reinterpret_cast<float2*>(g_dist + ig * N + jg) = make_float2(d0, d1);
        g_dist[(jg    ) * N + ig] = d0;   // mirror (diag: same-value dup, benign)
        g_dist[(jg + 1) * N + ig] = d1;
    }
}

// ---------------------------------------------------------------------------
// Kernel 2: triplet reduction, 128 blocks x 4 anchors, fused final reduce.
// ---------------------------------------------------------------------------
__global__ void triplet_kernel(const int* __restrict__ labels,
                               float* __restrict__ out) {
    __shared__ float drow[4 * N];     // 4 contiguous dist rows
    __shared__ int   lab[N];
    __shared__ int   segcnt[16];
    __shared__ int   posj[N];
    __shared__ int   s_npos;
    __shared__ float sred[8];
    __shared__ int   cred[8];
    __shared__ float fsred[8];
    __shared__ float fcred[8];
    __shared__ int   s_last;

    const int t = threadIdx.x;        // 0..255
    const int lane = t & 31;
    const int w = t >> 5;
    const int a0 = blockIdx.x * 4;

    // rows a0..a0+3 contiguous in g_dist -> one coalesced stream
    {
        const float4* src = reinterpret_cast<const float4*>(g_dist + a0 * N);
        float4* dst = reinterpret_cast<float4*>(drow);
        dst[t] = src[t];
        dst[t + 256] = src[t + 256];
        reinterpret_cast<int2*>(lab)[t] = reinterpret_cast<const int2*>(labels)[t];
    }
    __syncthreads();

    float tsum = 0.f;
    int tcnt = 0;

#pragma unroll
    for (int r = 0; r < 4; r++) {
        const int a = a0 + r;
        const int li = lab[a];
        const float* dr = drow + r * N;

        const bool m0 = (lab[t] == li) && (t != a);
        const bool m1 = (lab[t + 256] == li) && (t + 256 != a);

        unsigned b0 = __ballot_sync(FULL, m0);
        unsigned b1 = __ballot_sync(FULL, m1);
        if (lane == 0) { segcnt[w] = __popc(b0); segcnt[8 + w] = __popc(b1); }
        __syncthreads();
        if (m0) {
            int off = 0;
            for (int s = 0; s < w; s++) off += segcnt[s];
            off += __popc(b0 & ((1u << lane) - 1u));
            posj[off] = t;
        }
        if (m1) {
            int off = 0;
            for (int s = 0; s < 8 + w; s++) off += segcnt[s];
            off += __popc(b1 & ((1u << lane) - 1u));
            posj[off] = t + 256;
        }
        if (t == 0) {
            int tot = 0;
            for (int s = 0; s < 16; s++) tot += segcnt[s];
            s_npos = tot;
        }
        __syncthreads();

        const int npos = s_npos;
        const float d0 = dr[t];
        const float d1 = dr[t + 256];
        const bool n0 = (lab[t] != li);
        const bool n1 = (lab[t + 256] != li);

        for (int p = 0; p < npos; p++) {
            float aa = dr[posj[p]] + 1.0f;   // d_ij + margin, smem broadcast
            if (n0) {
                float v = aa - d0;
                if (v > 0.f) tsum += v;
                if (v > 1e-16f) tcnt++;
            }
            if (n1) {
                float v = aa - d1;
                if (v > 0.f) tsum += v;
                if (v > 1e-16f) tcnt++;
            }
        }
        __syncthreads();                     // before segcnt/posj reuse
    }

    // one deterministic block reduction for all 4 anchors
#pragma unroll
    for (int o = 16; o > 0; o >>= 1) {
        tsum += __shfl_down_sync(FULL, tsum, o);
        tcnt += __shfl_down_sync(FULL, tcnt, o);
    }
    if (lane == 0) { sred[w] = tsum; cred[w] = tcnt; }
    __syncthreads();
    if (t == 0) {
        float s = 0.f; int c = 0;
#pragma unroll
        for (int k = 0; k < 8; k++) { s += sred[k]; c += cred[k]; }
        g_psum[blockIdx.x] = s;
        g_pcnt[blockIdx.x] = (float)c;
        __threadfence();
        int old = atomicAdd(&g_done, 1);
        s_last = (old == NBLK_T - 1) ? 1 : 0;
    }
    __syncthreads();

    if (s_last) {
        __threadfence();
        float s = (t < NBLK_T) ? g_psum[t] : 0.f;
        float c = (t < NBLK_T) ? g_pcnt[t] : 0.f;
#pragma unroll
        for (int o = 16; o > 0; o >>= 1) {
            s += __shfl_down_sync(FULL, s, o);
            c += __shfl_down_sync(FULL, c, o);
        }
        if (lane == 0) { fsred[w] = s; fcred[w] = c; }
        __syncthreads();
        if (t == 0) {
            float S = 0.f, C = 0.f;
#pragma unroll
            for (int k = 0; k < 8; k++) { S += fsred[k]; C += fcred[k]; }
            out[0] = S / (C + 1e-16f);
            g_done = 0;                      // reset for next graph replay
        }
    }
}

// ---------------------------------------------------------------------------
extern "C" void kernel_launch(void* const* d_in, const int* in_sizes, int n_in,
                              void* d_out, int out_size) {
    const float* x      = (const float*)d_in[0];   // (512, 256) float32
    const int*   labels = (const int*)d_in[1];     // (512,) int32
    float* out = (float*)d_out;

    dist_kernel<<<NBLK_D, 128>>>(x);
    triplet_kernel<<<NBLK_T, 256>>>(labels, out);
}